// round 10
// baseline (speedup 1.0000x reference)
#include <cuda_runtime.h>
#include <cuda_bf16.h>

// ---------------- problem constants ----------------
#define NLAY 15
#define BB   2
#define LL   2048
#define DM   512
#define DI   1024
#define DS   16
#define DTR  32
#define NCH  32        // L / BLOCK
#define BLKT 64        // BLOCK
#define TT   65        // BLOCK + 1 (state token)
#define RWS  130       // BB * TT

// ---------------- static scratch ----------------
__device__ float g_co  [NCH*BB*BLKT*DM];
__device__ float g_cwc [NLAY*RWS*DM];
__device__ float g_xz  [NLAY*RWS*2*DI];
__device__ float g_xc  [NLAY*RWS*DI];
__device__ float g_xdbl[NLAY*RWS*64];
__device__ float g_y   [NLAY*RWS*DI];
__device__ float g_state[NLAY*2*BB*DM];
__device__ float g_mem [BB*NCH*DM];
__device__ float g_A2  [NLAY*DS*DI];
__device__ float g_mamba[BB*LL*DM];
__device__ float g_q   [BB*LL*DM];
__device__ float g_k   [BB*NCH*DM];
__device__ float g_v   [BB*NCH*DM];
__device__ float g_ao  [BB*LL*DM];
__device__ float g_hres[BB*LL*DM];
__device__ float g_hf  [BB*LL*DM];
__device__ float g_WqT [DM*DM];
__device__ float g_WkT [DM*DM];
__device__ float g_WvT [DM*DM];
__device__ float g_WoT [DM*DM];

// ---------------- init kernels ----------------
__global__ void embed_k(const int* __restrict__ tok, const float* __restrict__ emb) {
    int id = blockIdx.x*256 + threadIdx.x;
    int c = id & 511; int rest = id >> 9;
    int l = rest & 2047; int b = rest >> 11;
    int i = l >> 6; int t = l & 63;
    int tv = tok[b*LL + l];
    g_co[((i*BB + b)*BLKT + t)*DM + c] = emb[tv*DM + c];
}

__global__ void a2_k(const float* __restrict__ alog) {
    int id = blockIdx.x*256 + threadIdx.x;
    int s = id & 15; int rest = id >> 4;
    int dch = rest & 1023; int j = rest >> 10;
    g_A2[(j*DS + s)*DI + dch] = -__expf(alog[id]);
}

__global__ void trans_k(const float* __restrict__ q, const float* __restrict__ k,
                        const float* __restrict__ v, const float* __restrict__ o) {
    int id = blockIdx.x*256 + threadIdx.x;
    int sel = id >> 18; int rem = id & 262143;
    int i = rem >> 9; int oo = rem & 511;
    const float* src = sel==0 ? q : sel==1 ? k : sel==2 ? v : o;
    float* dst = sel==0 ? g_WqT : sel==1 ? g_WkT : sel==2 ? g_WvT : g_WoT;
    dst[i*DM + oo] = src[oo*DM + i];
}

__global__ void sinit_k(const float* __restrict__ istate) {
    int id = blockIdx.x*256 + threadIdx.x;
    if (id >= NLAY*BB*DM) return;
    int c = id & 511; int b = (id >> 9) & 1; int j = id >> 10;
    g_state[((j*2 + 1)*BB + b)*DM + c] = istate[j*DM + c];
}

// ---------------- per-phase small kernels ----------------
__global__ void prep_k(int d, int i_min, int nrows, const float* __restrict__ rms_w) {
    int w = blockIdx.x*4 + (threadIdx.x >> 5);
    int lane = threadIdx.x & 31;
    if (w >= nrows) return;
    int cell = w / RWS; int rr = w - cell*RWS;
    int b = rr / TT;    int t  = rr - b*TT;
    int ci = i_min + cell; int cj = d - ci;
    float* dst = g_cwc + (cj*RWS + rr)*DM;
    if (t == 0) {
        const float* src = g_state + ((cj*2 + ((ci+1)&1))*BB + b)*DM;
        for (int c = lane; c < DM; c += 32) dst[c] = src[c];
    } else {
        const float* src = g_co + ((ci*BB + b)*BLKT + (t-1))*DM;
        float vals[16]; float ss = 0.f;
        #pragma unroll
        for (int k2 = 0; k2 < 16; k2++) { float v = src[lane + 32*k2]; vals[k2] = v; ss += v*v; }
        #pragma unroll
        for (int o = 16; o > 0; o >>= 1) ss += __shfl_xor_sync(0xffffffffu, ss, o);
        float scale = rsqrtf(ss * (1.0f/DM) + 1e-6f);
        #pragma unroll
        for (int k2 = 0; k2 < 16; k2++) {
            int c = lane + 32*k2;
            dst[c] = vals[k2] * scale * rms_w[cj*DM + c];
        }
    }
}

__global__ void conv_k(int d, int i_min, const float* __restrict__ cw, const float* __restrict__ cb) {
    int cell = blockIdx.y; int ci = i_min + cell; int cj = d - ci;
    int q = blockIdx.x*blockDim.x + threadIdx.x;
    if (q >= RWS*DI) return;
    int dch = q & (DI-1);
    int rq  = q >> 10;
    int b = rq / TT; int t = rq - b*TT;
    const float* xbase = g_xz + (cj*RWS + b*TT)*2*DI + dch;
    float acc = cb[cj*DI + dch];
    #pragma unroll
    for (int k2 = 0; k2 < 4; k2++) {
        int ts = t - 3 + k2;
        if (ts >= 0) acc += xbase[ts*2*DI] * cw[(cj*DI + dch)*4 + k2];
    }
    float s = 1.f/(1.f + __expf(-acc));
    g_xc[(cj*RWS + rq)*DI + dch] = acc * s;
}

__global__ void scan_k(int d, int i_min, const float* __restrict__ dtw,
                       const float* __restrict__ dtb, const float* __restrict__ Dsk) {
    __shared__ float sx[TT][64];
    int cell = blockIdx.x >> 4;
    int sub  = blockIdx.x & 15;
    int b  = sub >> 3; int cg = sub & 7;
    int ci = i_min + cell; int cj = d - ci;
    int tid = threadIdx.x;
    const float* xd = g_xdbl + (cj*RWS + b*TT)*64;
    for (int idx = tid; idx < TT*64; idx += 128) sx[idx >> 6][idx & 63] = xd[idx];
    __syncthreads();
    int dch = cg*128 + tid;
    float dtwr[32];
    #pragma unroll
    for (int r = 0; r < 32; r++) dtwr[r] = dtw[(cj*DTR + r)*DI + dch];
    float a2r[16];
    #pragma unroll
    for (int s = 0; s < 16; s++) a2r[s] = g_A2[(cj*DS + s)*DI + dch];
    float dtbv = dtb[cj*DI + dch];
    float dv   = Dsk[cj*DI + dch];
    float st[16];
    #pragma unroll
    for (int s = 0; s < 16; s++) st[s] = 0.f;
    const float* xcb = g_xc + (cj*RWS + b*TT)*DI + dch;
    const float* zb  = g_xz + (cj*RWS + b*TT)*2*DI + DI + dch;
    float* yb = g_y + (cj*RWS + b*TT)*DI + dch;
    for (int t = 0; t < TT; t++) {
        float v = dtbv;
        #pragma unroll
        for (int r = 0; r < 32; r++) v += sx[t][r] * dtwr[r];
        float dt = (v > 20.f) ? v : log1pf(__expf(v));
        float xcv = xcb[t*DI];
        float dx = dt * xcv;
        float yv = 0.f;
        #pragma unroll
        for (int s = 0; s < 16; s++) {
            float e = __expf(dt * a2r[s]);
            st[s] = st[s]*e + dx * sx[t][32+s];
            yv += st[s] * sx[t][48+s];
        }
        yv += dv * xcv;
        float z = zb[t*2*DI];
        float sg = 1.f/(1.f + __expf(-z));
        yb[t*DI] = yv * (z * sg);
    }
}

// ---------------- tf32 3-pass tensor-core GEMM ----------------
// Tile: 128(M) x 64(N), 8 warps (4x2), warp tile 32x32 = 2(m16) x 4(n8) mma.
// A split into hi/lo tf32 parts; D = ah*bh + ah*bl + al*bh  (~fp32 accuracy).
// MODE 10: W_in   MODE 11: x_proj  MODE 12: W_out(+scatter)
// MODE 20: q-proj MODE 23: attn-out(+res+mask)  MODE 24: head
#define MMA3(dd, aa, bb) \
    asm volatile("mma.sync.aligned.m16n8k8.row.col.f32.tf32.tf32.f32 " \
        "{%0,%1,%2,%3},{%4,%5,%6,%7},{%8,%9},{%0,%1,%2,%3};" \
        : "+f"(dd[0]), "+f"(dd[1]), "+f"(dd[2]), "+f"(dd[3]) \
        : "r"(aa[0]), "r"(aa[1]), "r"(aa[2]), "r"(aa[3]), "r"(bb[0]), "r"(bb[1]))

__device__ __forceinline__ unsigned cvt_tf32(float x) {
    unsigned u; asm("cvt.rna.tf32.f32 %0, %1;" : "=r"(u) : "f"(x)); return u;
}

template<int MODE>
__global__ void __launch_bounds__(256) mmagemm_k(const float* Bw, float* Cb,
                                                 const float* bias, int d, int i_min,
                                                 int N, int K) {
    int ci = 0, cj = 0;
    const float* A; const float* Bm; float* C = Cb;
    if (MODE == 10 || MODE == 11 || MODE == 12) {
        int cell = blockIdx.y; ci = i_min + cell; cj = d - ci;
    }
    if (MODE == 10)      { A = g_cwc + cj*RWS*DM; Bm = Bw + cj*DM*2*DI; C = g_xz  + cj*RWS*2*DI; }
    else if (MODE == 11) { A = g_xc  + cj*RWS*DI; Bm = Bw + cj*DI*64;   C = g_xdbl+ cj*RWS*64;   }
    else if (MODE == 12) { A = g_y   + cj*RWS*DI; Bm = Bw + cj*DI*DM;   C = nullptr;             }
    else if (MODE == 20) { A = g_mamba; Bm = g_WqT; C = g_q;    }
    else if (MODE == 23) { A = g_ao;    Bm = g_WoT; C = g_hres; }
    else                 { A = g_hf;    Bm = Bw;    C = Cb;     }  // 24

    int tilesN = N >> 6;
    int mT = blockIdx.x / tilesN, nT = blockIdx.x % tilesN;
    int row0 = mT*128, col0 = nT*64;

    __shared__ float As_hi[16*136], As_lo[16*136];
    __shared__ float Bs_hi[16*72],  Bs_lo[16*72];

    int tid = threadIdx.x;
    int wid = tid >> 5, lane = tid & 31;
    int wm = wid >> 1, wn = wid & 1;
    int g  = lane >> 2, c4 = lane & 3;

    float acc[2][4][4];
    #pragma unroll
    for (int mt = 0; mt < 2; mt++)
        #pragma unroll
        for (int nt = 0; nt < 4; nt++)
            #pragma unroll
            for (int e = 0; e < 4; e++) acc[mt][nt][e] = 0.f;

    int am = tid >> 1, ak = (tid & 1)*8;
    const float* aptr = A + (long)(row0 + am)*K + ak;
    int bk = tid >> 4, bn = (tid & 15)*4;
    const float* bptr = Bm + (long)bk*N + col0 + bn;

    for (int k0 = 0; k0 < K; k0 += 16) {
        float4 v0 = *(const float4*)(aptr + k0);
        float4 v1 = *(const float4*)(aptr + k0 + 4);
        float av[8] = {v0.x, v0.y, v0.z, v0.w, v1.x, v1.y, v1.z, v1.w};
        #pragma unroll
        for (int j = 0; j < 8; j++) {
            float hf = __uint_as_float(cvt_tf32(av[j]));
            As_hi[(ak + j)*136 + am] = hf;
            As_lo[(ak + j)*136 + am] = av[j] - hf;
        }
        float4 bv = *(const float4*)(bptr + (long)k0*N);
        float bvv[4] = {bv.x, bv.y, bv.z, bv.w};
        #pragma unroll
        for (int j = 0; j < 4; j++) {
            float hf = __uint_as_float(cvt_tf32(bvv[j]));
            Bs_hi[bk*72 + bn + j] = hf;
            Bs_lo[bk*72 + bn + j] = bvv[j] - hf;
        }
        __syncthreads();
        #pragma unroll
        for (int k8 = 0; k8 < 16; k8 += 8) {
            unsigned ah[2][4], al[2][4], bh[4][2], bl[4][2];
            int r0 = (k8 + c4)*136, r1 = (k8 + c4 + 4)*136;
            #pragma unroll
            for (int mt = 0; mt < 2; mt++) {
                int mr = wm*32 + mt*16 + g;
                ah[mt][0] = __float_as_uint(As_hi[r0 + mr]);
                ah[mt][1] = __float_as_uint(As_hi[r0 + mr + 8]);
                ah[mt][2] = __float_as_uint(As_hi[r1 + mr]);
                ah[mt][3] = __float_as_uint(As_hi[r1 + mr + 8]);
                al[mt][0] = __float_as_uint(As_lo[r0 + mr]);
                al[mt][1] = __float_as_uint(As_lo[r0 + mr + 8]);
                al[mt][2] = __float_as_uint(As_lo[r1 + mr]);
                al[mt][3] = __float_as_uint(As_lo[r1 + mr + 8]);
            }
            int q0 = (k8 + c4)*72, q1 = (k8 + c4 + 4)*72;
            #pragma unroll
            for (int nt = 0; nt < 4; nt++) {
                int ncl = wn*32 + nt*8 + g;
                bh[nt][0] = __float_as_uint(Bs_hi[q0 + ncl]);
                bh[nt][1] = __float_as_uint(Bs_hi[q1 + ncl]);
                bl[nt][0] = __float_as_uint(Bs_lo[q0 + ncl]);
                bl[nt][1] = __float_as_uint(Bs_lo[q1 + ncl]);
            }
            #pragma unroll
            for (int mt = 0; mt < 2; mt++)
                #pragma unroll
                for (int nt = 0; nt < 4; nt++) {
                    MMA3(acc[mt][nt], ah[mt], bh[nt]);
                    MMA3(acc[mt][nt], ah[mt], bl[nt]);
                    MMA3(acc[mt][nt], al[mt], bh[nt]);
                }
        }
        __syncthreads();
    }

    // epilogue
    #pragma unroll
    for (int mt = 0; mt < 2; mt++) {
        #pragma unroll
        for (int half = 0; half < 2; half++) {
            int gr = row0 + wm*32 + mt*16 + g + half*8;
            #pragma unroll
            for (int nt = 0; nt < 4; nt++) {
                int gc = col0 + wn*32 + nt*8 + c4*2;
                float va = acc[mt][nt][half*2 + 0];
                float vb = acc[mt][nt][half*2 + 1];
                if (MODE == 10 || MODE == 11 || MODE == 24) {
                    *(float2*)&C[(long)gr*N + gc] = make_float2(va, vb);
                } else if (MODE == 20) {
                    *(float2*)&C[(long)gr*N + gc] = make_float2(va + bias[gc], vb + bias[gc+1]);
                } else if (MODE == 23) {
                    int l = gr & (LL-1);
                    int tb = l >> 6;
                    float wa = (tb > 0) ? (va + bias[gc])   : 0.f;
                    float wb = (tb > 0) ? (vb + bias[gc+1]) : 0.f;
                    *(float2*)&C[(long)gr*N + gc] =
                        make_float2(g_mamba[(long)gr*DM + gc] + wa,
                                    g_mamba[(long)gr*DM + gc + 1] + wb);
                } else if (MODE == 12) {
                    int b = gr / TT; int tt = gr - b*TT;   // gr in [0,128)
                    if (tt > 0) {
                        g_co[((ci*BB + b)*BLKT + (tt-1))*DM + gc]     += va;
                        g_co[((ci*BB + b)*BLKT + (tt-1))*DM + gc + 1] += vb;
                    }
                    if (tt == TT-1) {
                        g_state[((cj*2 + (ci&1))*BB + b)*DM + gc]     = va;
                        g_state[((cj*2 + (ci&1))*BB + b)*DM + gc + 1] = vb;
                        if (cj == NLAY-1) {
                            g_mem[(b*NCH + ci)*DM + gc]     = va;
                            g_mem[(b*NCH + ci)*DM + gc + 1] = vb;
                        }
                    }
                }
            }
        }
    }
}

// rows 128,129 of each cell (b=1, t=63,64) — tiny FFMA tail
template<int MODE>
__global__ void tail_k(const float* Bw, int d, int i_min, int N, int K) {
    int cell = blockIdx.y; int ci = i_min + cell; int cj = d - ci;
    const float* A; const float* Bm;
    if (MODE == 10)      { A = g_cwc + cj*RWS*DM; Bm = Bw + cj*DM*2*DI; }
    else if (MODE == 11) { A = g_xc  + cj*RWS*DI; Bm = Bw + cj*DI*64;   }
    else                 { A = g_y   + cj*RWS*DI; Bm = Bw + cj*DI*DM;   }
    int col = blockIdx.x*128 + threadIdx.x;
    if (col >= N) return;
    const float* a0 = A + 128*K;
    const float* a1 = A + 129*K;
    float acc0 = 0.f, acc1 = 0.f;
    #pragma unroll 4
    for (int k = 0; k < K; k++) {
        float b = Bm[(long)k*N + col];
        acc0 += a0[k]*b; acc1 += a1[k]*b;
    }
    if (MODE == 10) {
        float* C = g_xz + cj*RWS*2*DI;
        C[128*N + col] = acc0; C[129*N + col] = acc1;
    } else if (MODE == 11) {
        float* C = g_xdbl + cj*RWS*64;
        C[128*N + col] = acc0; C[129*N + col] = acc1;
    } else {
        // gr=128 -> b=1,t=63 ; gr=129 -> b=1,t=64
        g_co[((ci*BB + 1)*BLKT + 62)*DM + col] += acc0;
        g_co[((ci*BB + 1)*BLKT + 63)*DM + col] += acc1;
        g_state[((cj*2 + (ci&1))*BB + 1)*DM + col] = acc1;
        if (cj == NLAY-1) g_mem[(1*NCH + ci)*DM + col] = acc1;
    }
}

// ---------------- small FFMA GEMM kept for k/v projections (M=64) ----------------
template<int MODE>
__global__ void gemm_k(const float* Ab, const float* Bb, float* Cb,
                       int M, int N, int K, const float* bias, int d, int i_min) {
    const float* A = Ab; const float* Bm = Bb; float* C = Cb;
    if (MODE == 21) { A = g_mem; Bm = g_WkT; C = g_k; }
    if (MODE == 22) { A = g_mem; Bm = g_WvT; C = g_v; }

    int tilesN = N >> 6;
    int mT = blockIdx.x / tilesN;
    int nT = blockIdx.x % tilesN;

    __shared__ float As[16][64];
    __shared__ float Bs[16][64];

    int tid = threadIdx.x;
    int ty = tid >> 4, tx = tid & 15;
    float acc[4][4];
    #pragma unroll
    for (int i2 = 0; i2 < 4; i2++)
        #pragma unroll
        for (int j2 = 0; j2 < 4; j2++) acc[i2][j2] = 0.f;

    int ar = tid >> 2, kq = tid & 3;
    int br = tid >> 4, nq = tid & 15;
    int grA = mT*64 + ar;
    const float* Aptr = A + (long)grA*K + kq*4;
    const float* Bptr = Bm + (long)br*N + nT*64 + nq*4;

    for (int k0 = 0; k0 < K; k0 += 16) {
        float4 av = make_float4(0.f,0.f,0.f,0.f);
        if (grA < M) av = *(const float4*)(Aptr + k0);
        float4 bv = *(const float4*)(Bptr + (long)k0*N);
        As[kq*4+0][ar] = av.x; As[kq*4+1][ar] = av.y;
        As[kq*4+2][ar] = av.z; As[kq*4+3][ar] = av.w;
        *(float4*)&Bs[br][nq*4] = bv;
        __syncthreads();
        #pragma unroll
        for (int kk = 0; kk < 16; kk++) {
            float4 a = *(float4*)&As[kk][ty*4];
            float4 b = *(float4*)&Bs[kk][tx*4];
            acc[0][0] += a.x*b.x; acc[0][1] += a.x*b.y; acc[0][2] += a.x*b.z; acc[0][3] += a.x*b.w;
            acc[1][0] += a.y*b.x; acc[1][1] += a.y*b.y; acc[1][2] += a.y*b.z; acc[1][3] += a.y*b.w;
            acc[2][0] += a.z*b.x; acc[2][1] += a.z*b.y; acc[2][2] += a.z*b.z; acc[2][3] += a.z*b.w;
            acc[3][0] += a.w*b.x; acc[3][1] += a.w*b.y; acc[3][2] += a.w*b.z; acc[3][3] += a.w*b.w;
        }
        __syncthreads();
    }

    #pragma unroll
    for (int ii = 0; ii < 4; ii++) {
        int gr = mT*64 + ty*4 + ii;
        if (gr >= M) continue;
        #pragma unroll
        for (int jj = 0; jj < 4; jj++) {
            int gc = nT*64 + tx*4 + jj;
            C[(long)gr*N + gc] = acc[ii][jj] + bias[gc];
        }
    }
}

// ---------------- tail kernels ----------------
__global__ void reorder_k() {
    int id = blockIdx.x*256 + threadIdx.x;
    int c = id & 511; int rest = id >> 9;
    int l = rest & 2047; int b = rest >> 11;
    int i = l >> 6; int t = l & 63;
    g_mamba[id] = g_co[((i*BB + b)*BLKT + t)*DM + c];
}

__global__ void attn_k() {
    int w = blockIdx.x*8 + (threadIdx.x >> 5);
    int lane = threadIdx.x & 31;
    int b = w >> 13; int rem = w & 8191;
    int l = rem >> 2; int h = rem & 3;
    int tb = l >> 6;
    float* aoRow = g_ao + ((long)b*LL + l)*DM + h*128;
    if (tb == 0) {
        #pragma unroll
        for (int e = 0; e < 4; e++) aoRow[lane + 32*e] = 0.f;
        return;
    }
    const float* qr = g_q + ((long)b*LL + l)*DM + h*128;
    float sc = -1e30f;
    if (lane < tb) {
        const float* kr = g_k + (b*NCH + lane)*DM + h*128;
        float s = 0.f;
        #pragma unroll 4
        for (int kk = 0; kk < 128; kk++) s += qr[kk]*kr[kk];
        sc = s * 0.08838834764831845f;
    }
    float mx = sc;
    #pragma unroll
    for (int o = 16; o > 0; o >>= 1) mx = fmaxf(mx, __shfl_xor_sync(0xffffffffu, mx, o));
    float p = (lane < tb) ? __expf(sc - mx) : 0.f;
    float sum = p;
    #pragma unroll
    for (int o = 16; o > 0; o >>= 1) sum += __shfl_xor_sync(0xffffffffu, sum, o);
    float a = p / sum;
    float accv[4] = {0.f,0.f,0.f,0.f};
    for (int mm = 0; mm < tb; mm++) {
        float am = __shfl_sync(0xffffffffu, a, mm);
        const float* vr = g_v + (b*NCH + mm)*DM + h*128;
        #pragma unroll
        for (int e = 0; e < 4; e++) accv[e] += am * vr[lane + 32*e];
    }
    #pragma unroll
    for (int e = 0; e < 4; e++) aoRow[lane + 32*e] = accv[e];
}

__global__ void ln_k(const float* __restrict__ lw, const float* __restrict__ lb) {
    int r = blockIdx.x*4 + (threadIdx.x >> 5);
    int lane = threadIdx.x & 31;
    const float* src = g_hres + (long)r*DM;
    float vals[16]; float s1 = 0.f, s2 = 0.f;
    #pragma unroll
    for (int k2 = 0; k2 < 16; k2++) { float v = src[lane + 32*k2]; vals[k2] = v; s1 += v; s2 += v*v; }
    #pragma unroll
    for (int o = 16; o > 0; o >>= 1) {
        s1 += __shfl_xor_sync(0xffffffffu, s1, o);
        s2 += __shfl_xor_sync(0xffffffffu, s2, o);
    }
    float mu = s1 * (1.0f/DM);
    float var = s2 * (1.0f/DM) - mu*mu;
    float is = rsqrtf(var + 1e-5f);
    #pragma unroll
    for (int k2 = 0; k2 < 16; k2++) {
        int c = lane + 32*k2;
        g_hf[(long)r*DM + c] = (vals[k2] - mu)*is*lw[c] + lb[c];
    }
}

// ---------------- launcher ----------------
extern "C" void kernel_launch(void* const* d_in, const int* in_sizes, int n_in,
                              void* d_out, int out_size) {
    const int*   tokens = (const int*)  d_in[0];
    const float* embed  = (const float*)d_in[1];
    const float* rms_w  = (const float*)d_in[2];
    const float* W_in   = (const float*)d_in[3];
    const float* conv_w = (const float*)d_in[4];
    const float* conv_b = (const float*)d_in[5];
    const float* x_proj = (const float*)d_in[6];
    const float* dt_w   = (const float*)d_in[7];
    const float* dt_b   = (const float*)d_in[8];
    const float* A_log  = (const float*)d_in[9];
    const float* D_skip = (const float*)d_in[10];
    const float* W_out  = (const float*)d_in[11];
    const float* init_state = (const float*)d_in[12];
    const float* Wq = (const float*)d_in[13];
    const float* Wk = (const float*)d_in[14];
    const float* Wv = (const float*)d_in[15];
    const float* bq = (const float*)d_in[16];
    const float* bk = (const float*)d_in[17];
    const float* bv = (const float*)d_in[18];
    const float* Wo = (const float*)d_in[19];
    const float* bo = (const float*)d_in[20];
    const float* ln_w = (const float*)d_in[21];
    const float* ln_b = (const float*)d_in[22];
    const float* head_w = (const float*)d_in[23];
    float* out = (float*)d_out;

    embed_k<<<8192, 256>>>(tokens, embed);
    a2_k  <<<960,  256>>>(A_log);
    trans_k<<<4096, 256>>>(Wq, Wk, Wv, Wo);
    sinit_k<<<60,   256>>>(init_state);

    for (int d = 0; d < NCH + NLAY - 1; d++) {
        int i_min = d - (NLAY - 1); if (i_min < 0) i_min = 0;
        int i_max = (d < NCH - 1) ? d : NCH - 1;
        int nc = i_max - i_min + 1;
        prep_k<<<(nc*RWS + 3)/4, 128>>>(d, i_min, nc*RWS, rms_w);
        mmagemm_k<10><<<dim3(32, nc), 256>>>(W_in, nullptr, nullptr, d, i_min, 2*DI, DM);
        tail_k<10><<<dim3(16, nc), 128>>>(W_in, d, i_min, 2*DI, DM);
        conv_k<<<dim3(520, nc), 256>>>(d, i_min, conv_w, conv_b);
        mmagemm_k<11><<<dim3(1, nc), 256>>>(x_proj, nullptr, nullptr, d, i_min, 64, DI);
        tail_k<11><<<dim3(1, nc), 128>>>(x_proj, d, i_min, 64, DI);
        scan_k<<<nc*16, 128>>>(d, i_min, dt_w, dt_b, D_skip);
        mmagemm_k<12><<<dim3(8, nc), 256>>>(W_out, nullptr, nullptr, d, i_min, DM, DI);
        tail_k<12><<<dim3(4, nc), 128>>>(W_out, d, i_min, DM, DI);
    }

    reorder_k<<<8192, 256>>>();
    mmagemm_k<20><<<256, 256>>>(nullptr, nullptr, bq, 0, 0, DM, DM);
    gemm_k<21><<<8,   256>>>(nullptr, nullptr, nullptr, BB*NCH, DM, DM, bk, 0, 0);
    gemm_k<22><<<8,   256>>>(nullptr, nullptr, nullptr, BB*NCH, DM, DM, bv, 0, 0);
    attn_k<<<2048, 256>>>();
    mmagemm_k<23><<<256, 256>>>(nullptr, nullptr, bo, 0, 0, DM, DM);
    ln_k<<<1024, 128>>>(ln_w, ln_b);
    mmagemm_k<24><<<256, 256>>>(head_w, out, nullptr, 0, 0, DM, DM);
}

// round 11
// speedup vs baseline: 1.0360x; 1.0360x over previous
#include <cuda_runtime.h>
#include <cuda_bf16.h>

// ---------------- problem constants ----------------
#define NLAY 15
#define BB   2
#define LL   2048
#define DM   512
#define DI   1024
#define DS   16
#define DTR  32
#define NCH  32        // L / BLOCK
#define BLKT 64        // BLOCK
#define TT   65        // BLOCK + 1 (state token)
#define RWS  130       // BB * TT

// ---------------- static scratch ----------------
__device__ float g_co  [NCH*BB*BLKT*DM];
__device__ float g_cwc [NLAY*RWS*DM];
__device__ float g_xz  [NLAY*RWS*2*DI];
__device__ float g_xc  [NLAY*RWS*DI];
__device__ float g_xdbl[NLAY*RWS*64];
__device__ float g_y   [NLAY*RWS*DI];
__device__ float g_state[NLAY*2*BB*DM];
__device__ float g_mem [BB*NCH*DM];
__device__ float g_A2  [NLAY*DS*DI];
__device__ float g_mamba[BB*LL*DM];
__device__ float g_q   [BB*LL*DM];
__device__ float g_k   [BB*NCH*DM];
__device__ float g_v   [BB*NCH*DM];
__device__ float g_ao  [BB*LL*DM];
__device__ float g_hres[BB*LL*DM];
__device__ float g_hf  [BB*LL*DM];
__device__ float g_WqT [DM*DM];
__device__ float g_WkT [DM*DM];
__device__ float g_WvT [DM*DM];
__device__ float g_WoT [DM*DM];

// ---------------- init kernels ----------------
__global__ void embed_k(const int* __restrict__ tok, const float* __restrict__ emb) {
    int id = blockIdx.x*256 + threadIdx.x;
    int c = id & 511; int rest = id >> 9;
    int l = rest & 2047; int b = rest >> 11;
    int i = l >> 6; int t = l & 63;
    int tv = tok[b*LL + l];
    g_co[((i*BB + b)*BLKT + t)*DM + c] = emb[tv*DM + c];
}

__global__ void a2_k(const float* __restrict__ alog) {
    int id = blockIdx.x*256 + threadIdx.x;
    int s = id & 15; int rest = id >> 4;
    int dch = rest & 1023; int j = rest >> 10;
    g_A2[(j*DS + s)*DI + dch] = -__expf(alog[id]);
}

__global__ void trans_k(const float* __restrict__ q, const float* __restrict__ k,
                        const float* __restrict__ v, const float* __restrict__ o) {
    int id = blockIdx.x*256 + threadIdx.x;
    int sel = id >> 18; int rem = id & 262143;
    int i = rem >> 9; int oo = rem & 511;
    const float* src = sel==0 ? q : sel==1 ? k : sel==2 ? v : o;
    float* dst = sel==0 ? g_WqT : sel==1 ? g_WkT : sel==2 ? g_WvT : g_WoT;
    dst[i*DM + oo] = src[oo*DM + i];
}

__global__ void sinit_k(const float* __restrict__ istate) {
    int id = blockIdx.x*256 + threadIdx.x;
    if (id >= NLAY*BB*DM) return;
    int c = id & 511; int b = (id >> 9) & 1; int j = id >> 10;
    g_state[((j*2 + 1)*BB + b)*DM + c] = istate[j*DM + c];
}

// ---------------- per-phase small kernels ----------------
__global__ void prep_k(int d, int i_min, int nrows, const float* __restrict__ rms_w) {
    int w = blockIdx.x*4 + (threadIdx.x >> 5);
    int lane = threadIdx.x & 31;
    if (w >= nrows) return;
    int cell = w / RWS; int rr = w - cell*RWS;
    int b = rr / TT;    int t  = rr - b*TT;
    int ci = i_min + cell; int cj = d - ci;
    float* dst = g_cwc + (cj*RWS + rr)*DM;
    if (t == 0) {
        const float* src = g_state + ((cj*2 + ((ci+1)&1))*BB + b)*DM;
        for (int c = lane; c < DM; c += 32) dst[c] = src[c];
    } else {
        const float* src = g_co + ((ci*BB + b)*BLKT + (t-1))*DM;
        float vals[16]; float ss = 0.f;
        #pragma unroll
        for (int k2 = 0; k2 < 16; k2++) { float v = src[lane + 32*k2]; vals[k2] = v; ss += v*v; }
        #pragma unroll
        for (int o = 16; o > 0; o >>= 1) ss += __shfl_xor_sync(0xffffffffu, ss, o);
        float scale = rsqrtf(ss * (1.0f/DM) + 1e-6f);
        #pragma unroll
        for (int k2 = 0; k2 < 16; k2++) {
            int c = lane + 32*k2;
            dst[c] = vals[k2] * scale * rms_w[cj*DM + c];
        }
    }
}

__global__ void conv_k(int d, int i_min, const float* __restrict__ cw, const float* __restrict__ cb) {
    int cell = blockIdx.y; int ci = i_min + cell; int cj = d - ci;
    int q = blockIdx.x*blockDim.x + threadIdx.x;
    if (q >= RWS*DI) return;
    int dch = q & (DI-1);
    int rq  = q >> 10;
    int b = rq / TT; int t = rq - b*TT;
    const float* xbase = g_xz + (cj*RWS + b*TT)*2*DI + dch;
    float acc = cb[cj*DI + dch];
    #pragma unroll
    for (int k2 = 0; k2 < 4; k2++) {
        int ts = t - 3 + k2;
        if (ts >= 0) acc += xbase[ts*2*DI] * cw[(cj*DI + dch)*4 + k2];
    }
    float s = 1.f/(1.f + __expf(-acc));
    g_xc[(cj*RWS + rq)*DI + dch] = acc * s;
}

__global__ void scan_k(int d, int i_min, const float* __restrict__ dtw,
                       const float* __restrict__ dtb, const float* __restrict__ Dsk) {
    __shared__ float sx[TT][64];
    int cell = blockIdx.x >> 4;
    int sub  = blockIdx.x & 15;
    int b  = sub >> 3; int cg = sub & 7;
    int ci = i_min + cell; int cj = d - ci;
    int tid = threadIdx.x;
    const float* xd = g_xdbl + (cj*RWS + b*TT)*64;
    for (int idx = tid; idx < TT*64; idx += 128) sx[idx >> 6][idx & 63] = xd[idx];
    __syncthreads();
    int dch = cg*128 + tid;
    float dtwr[32];
    #pragma unroll
    for (int r = 0; r < 32; r++) dtwr[r] = dtw[(cj*DTR + r)*DI + dch];
    float a2r[16];
    #pragma unroll
    for (int s = 0; s < 16; s++) a2r[s] = g_A2[(cj*DS + s)*DI + dch];
    float dtbv = dtb[cj*DI + dch];
    float dv   = Dsk[cj*DI + dch];
    float st[16];
    #pragma unroll
    for (int s = 0; s < 16; s++) st[s] = 0.f;
    const float* xcb = g_xc + (cj*RWS + b*TT)*DI + dch;
    const float* zb  = g_xz + (cj*RWS + b*TT)*2*DI + DI + dch;
    float* yb = g_y + (cj*RWS + b*TT)*DI + dch;
    for (int t = 0; t < TT; t++) {
        float v = dtbv;
        #pragma unroll
        for (int r = 0; r < 32; r++) v += sx[t][r] * dtwr[r];
        float dt = (v > 20.f) ? v : log1pf(__expf(v));
        float xcv = xcb[t*DI];
        float dx = dt * xcv;
        float yv = 0.f;
        #pragma unroll
        for (int s = 0; s < 16; s++) {
            float e = __expf(dt * a2r[s]);
            st[s] = st[s]*e + dx * sx[t][32+s];
            yv += st[s] * sx[t][48+s];
        }
        yv += dv * xcv;
        float z = zb[t*2*DI];
        float sg = 1.f/(1.f + __expf(-z));
        yb[t*DI] = yv * (z * sg);
    }
}

// ---------------- high-throughput fp32 FFMA GEMM ----------------
// Tile 128(M) x 64(N), BK=16, 256 threads, 8x4 micro-tile per thread.
// Double-buffered smem, ONE __syncthreads per K-tile, global loads software-
// pipelined into registers. A-frag reads are warp-broadcast; B conflict-free.
// MODE 10: W_in   MODE 11: x_proj  MODE 12: W_out(+scatter)
// MODE 20: q-proj MODE 23: attn-out(+res+mask)  MODE 24: head
template<int MODE>
__global__ void __launch_bounds__(256) fgemm_k(const float* Bw, float* Cb,
                                               const float* bias, int d, int i_min,
                                               int N, int K) {
    int ci = 0, cj = 0;
    const float* A; const float* Bm; float* C = Cb;
    if (MODE == 10 || MODE == 11 || MODE == 12) {
        int cell = blockIdx.y; ci = i_min + cell; cj = d - ci;
    }
    if (MODE == 10)      { A = g_cwc + cj*RWS*DM; Bm = Bw + cj*DM*2*DI; C = g_xz  + cj*RWS*2*DI; }
    else if (MODE == 11) { A = g_xc  + cj*RWS*DI; Bm = Bw + cj*DI*64;   C = g_xdbl+ cj*RWS*64;   }
    else if (MODE == 12) { A = g_y   + cj*RWS*DI; Bm = Bw + cj*DI*DM;   C = nullptr;             }
    else if (MODE == 20) { A = g_mamba; Bm = g_WqT; C = g_q;    }
    else if (MODE == 23) { A = g_ao;    Bm = g_WoT; C = g_hres; }
    else                 { A = g_hf;    Bm = Bw;    C = Cb;     }  // 24

    int tilesN = N >> 6;
    int mT = blockIdx.x / tilesN, nT = blockIdx.x % tilesN;
    int row0 = mT*128, col0 = nT*64;

    __shared__ float As[2][16][128];
    __shared__ float Bs[2][16][64];

    int tid = threadIdx.x;
    int tx = tid & 15, ty = tid >> 4;            // compute layout: 8 rows x 4 cols

    int ar = tid >> 1, kq = (tid & 1)*8;         // A staging: 2 thr/row, 8 k each
    int br = tid >> 4, bn = (tid & 15)*4;        // B staging

    const float* aptr = A + (long)(row0 + ar)*K + kq;
    const float* bptr = Bm + (long)br*N + col0 + bn;

    float acc[8][4];
    #pragma unroll
    for (int i2 = 0; i2 < 8; i2++)
        #pragma unroll
        for (int j2 = 0; j2 < 4; j2++) acc[i2][j2] = 0.f;

    // prologue: tile 0 -> smem buf 0
    {
        float4 a0 = *(const float4*)(aptr);
        float4 a1 = *(const float4*)(aptr + 4);
        float4 bv = *(const float4*)(bptr);
        As[0][kq+0][ar] = a0.x; As[0][kq+1][ar] = a0.y;
        As[0][kq+2][ar] = a0.z; As[0][kq+3][ar] = a0.w;
        As[0][kq+4][ar] = a1.x; As[0][kq+5][ar] = a1.y;
        As[0][kq+6][ar] = a1.z; As[0][kq+7][ar] = a1.w;
        *(float4*)&Bs[0][br][bn] = bv;
    }
    __syncthreads();

    int buf = 0;
    for (int k0 = 0; k0 < K; k0 += 16) {
        bool hasnext = (k0 + 16) < K;
        float4 na0, na1, nbv;
        if (hasnext) {
            na0 = *(const float4*)(aptr + k0 + 16);
            na1 = *(const float4*)(aptr + k0 + 20);
            nbv = *(const float4*)(bptr + (long)(k0 + 16)*N);
        }
        #pragma unroll
        for (int kk = 0; kk < 16; kk++) {
            float4 af0 = *(const float4*)&As[buf][kk][ty*8];
            float4 af1 = *(const float4*)&As[buf][kk][ty*8 + 4];
            float4 bf  = *(const float4*)&Bs[buf][kk][tx*4];
            float a_[8] = {af0.x, af0.y, af0.z, af0.w, af1.x, af1.y, af1.z, af1.w};
            float b_[4] = {bf.x, bf.y, bf.z, bf.w};
            #pragma unroll
            for (int i2 = 0; i2 < 8; i2++)
                #pragma unroll
                for (int j2 = 0; j2 < 4; j2++)
                    acc[i2][j2] += a_[i2]*b_[j2];
        }
        if (hasnext) {
            int nb2 = buf ^ 1;
            As[nb2][kq+0][ar] = na0.x; As[nb2][kq+1][ar] = na0.y;
            As[nb2][kq+2][ar] = na0.z; As[nb2][kq+3][ar] = na0.w;
            As[nb2][kq+4][ar] = na1.x; As[nb2][kq+5][ar] = na1.y;
            As[nb2][kq+6][ar] = na1.z; As[nb2][kq+7][ar] = na1.w;
            *(float4*)&Bs[nb2][br][bn] = nbv;
            __syncthreads();
            buf = nb2;
        }
    }

    // epilogue
    #pragma unroll
    for (int ii = 0; ii < 8; ii++) {
        int gr = row0 + ty*8 + ii;
        int gc = col0 + tx*4;
        if (MODE == 10 || MODE == 11 || MODE == 24) {
            *(float4*)&C[(long)gr*N + gc] =
                make_float4(acc[ii][0], acc[ii][1], acc[ii][2], acc[ii][3]);
        } else if (MODE == 20) {
            *(float4*)&C[(long)gr*N + gc] =
                make_float4(acc[ii][0] + bias[gc],   acc[ii][1] + bias[gc+1],
                            acc[ii][2] + bias[gc+2], acc[ii][3] + bias[gc+3]);
        } else if (MODE == 23) {
            int l = gr & (LL-1);
            int tb = l >> 6;
            const float* mb = &g_mamba[(long)gr*DM + gc];
            float4 mv = *(const float4*)mb;
            float4 ov;
            if (tb > 0) {
                ov = make_float4(mv.x + acc[ii][0] + bias[gc],
                                 mv.y + acc[ii][1] + bias[gc+1],
                                 mv.z + acc[ii][2] + bias[gc+2],
                                 mv.w + acc[ii][3] + bias[gc+3]);
            } else {
                ov = mv;
            }
            *(float4*)&C[(long)gr*N + gc] = ov;
        } else if (MODE == 12) {
            int b = gr / TT; int tt = gr - b*TT;   // gr in [0,128)
            if (tt > 0) {
                float* dst = &g_co[((ci*BB + b)*BLKT + (tt-1))*DM + gc];
                dst[0] += acc[ii][0]; dst[1] += acc[ii][1];
                dst[2] += acc[ii][2]; dst[3] += acc[ii][3];
            }
            if (tt == TT-1) {
                float* sdst = &g_state[((cj*2 + (ci&1))*BB + b)*DM + gc];
                sdst[0] = acc[ii][0]; sdst[1] = acc[ii][1];
                sdst[2] = acc[ii][2]; sdst[3] = acc[ii][3];
                if (cj == NLAY-1) {
                    float* mdst = &g_mem[(b*NCH + ci)*DM + gc];
                    mdst[0] = acc[ii][0]; mdst[1] = acc[ii][1];
                    mdst[2] = acc[ii][2]; mdst[3] = acc[ii][3];
                }
            }
        }
    }
}

// rows 128,129 of each cell (b=1, t=63,64) — tiny FFMA tail
template<int MODE>
__global__ void tail_k(const float* Bw, int d, int i_min, int N, int K) {
    int cell = blockIdx.y; int ci = i_min + cell; int cj = d - ci;
    const float* A; const float* Bm;
    if (MODE == 10)      { A = g_cwc + cj*RWS*DM; Bm = Bw + cj*DM*2*DI; }
    else if (MODE == 11) { A = g_xc  + cj*RWS*DI; Bm = Bw + cj*DI*64;   }
    else                 { A = g_y   + cj*RWS*DI; Bm = Bw + cj*DI*DM;   }
    int col = blockIdx.x*128 + threadIdx.x;
    if (col >= N) return;
    const float* a0 = A + 128*K;
    const float* a1 = A + 129*K;
    float acc0 = 0.f, acc1 = 0.f;
    #pragma unroll 4
    for (int k = 0; k < K; k++) {
        float b = Bm[(long)k*N + col];
        acc0 += a0[k]*b; acc1 += a1[k]*b;
    }
    if (MODE == 10) {
        float* C = g_xz + cj*RWS*2*DI;
        C[128*N + col] = acc0; C[129*N + col] = acc1;
    } else if (MODE == 11) {
        float* C = g_xdbl + cj*RWS*64;
        C[128*N + col] = acc0; C[129*N + col] = acc1;
    } else {
        g_co[((ci*BB + 1)*BLKT + 62)*DM + col] += acc0;
        g_co[((ci*BB + 1)*BLKT + 63)*DM + col] += acc1;
        g_state[((cj*2 + (ci&1))*BB + 1)*DM + col] = acc1;
        if (cj == NLAY-1) g_mem[(1*NCH + ci)*DM + col] = acc1;
    }
}

// ---------------- small FFMA GEMM for k/v projections (M=64) ----------------
template<int MODE>
__global__ void gemm_k(const float* Ab, const float* Bb, float* Cb,
                       int M, int N, int K, const float* bias, int d, int i_min) {
    const float* A = Ab; const float* Bm = Bb; float* C = Cb;
    if (MODE == 21) { A = g_mem; Bm = g_WkT; C = g_k; }
    if (MODE == 22) { A = g_mem; Bm = g_WvT; C = g_v; }

    int tilesN = N >> 6;
    int mT = blockIdx.x / tilesN;
    int nT = blockIdx.x % tilesN;

    __shared__ float As[16][64];
    __shared__ float Bs[16][64];

    int tid = threadIdx.x;
    int ty = tid >> 4, tx = tid & 15;
    float acc[4][4];
    #pragma unroll
    for (int i2 = 0; i2 < 4; i2++)
        #pragma unroll
        for (int j2 = 0; j2 < 4; j2++) acc[i2][j2] = 0.f;

    int ar = tid >> 2, kq = tid & 3;
    int br = tid >> 4, nq = tid & 15;
    int grA = mT*64 + ar;
    const float* Aptr = A + (long)grA*K + kq*4;
    const float* Bptr = Bm + (long)br*N + nT*64 + nq*4;

    for (int k0 = 0; k0 < K; k0 += 16) {
        float4 av = make_float4(0.f,0.f,0.f,0.f);
        if (grA < M) av = *(const float4*)(Aptr + k0);
        float4 bv = *(const float4*)(Bptr + (long)k0*N);
        As[kq*4+0][ar] = av.x; As[kq*4+1][ar] = av.y;
        As[kq*4+2][ar] = av.z; As[kq*4+3][ar] = av.w;
        *(float4*)&Bs[br][nq*4] = bv;
        __syncthreads();
        #pragma unroll
        for (int kk = 0; kk < 16; kk++) {
            float4 a = *(float4*)&As[kk][ty*4];
            float4 b = *(float4*)&Bs[kk][tx*4];
            acc[0][0] += a.x*b.x; acc[0][1] += a.x*b.y; acc[0][2] += a.x*b.z; acc[0][3] += a.x*b.w;
            acc[1][0] += a.y*b.x; acc[1][1] += a.y*b.y; acc[1][2] += a.y*b.z; acc[1][3] += a.y*b.w;
            acc[2][0] += a.z*b.x; acc[2][1] += a.z*b.y; acc[2][2] += a.z*b.z; acc[2][3] += a.z*b.w;
            acc[3][0] += a.w*b.x; acc[3][1] += a.w*b.y; acc[3][2] += a.w*b.z; acc[3][3] += a.w*b.w;
        }
        __syncthreads();
    }

    #pragma unroll
    for (int ii = 0; ii < 4; ii++) {
        int gr = mT*64 + ty*4 + ii;
        if (gr >= M) continue;
        #pragma unroll
        for (int jj = 0; jj < 4; jj++) {
            int gc = nT*64 + tx*4 + jj;
            C[(long)gr*N + gc] = acc[ii][jj] + bias[gc];
        }
    }
}

// ---------------- tail kernels ----------------
__global__ void reorder_k() {
    int id = blockIdx.x*256 + threadIdx.x;
    int c = id & 511; int rest = id >> 9;
    int l = rest & 2047; int b = rest >> 11;
    int i = l >> 6; int t = l & 63;
    g_mamba[id] = g_co[((i*BB + b)*BLKT + t)*DM + c];
}

__global__ void attn_k() {
    int w = blockIdx.x*8 + (threadIdx.x >> 5);
    int lane = threadIdx.x & 31;
    int b = w >> 13; int rem = w & 8191;
    int l = rem >> 2; int h = rem & 3;
    int tb = l >> 6;
    float* aoRow = g_ao + ((long)b*LL + l)*DM + h*128;
    if (tb == 0) {
        #pragma unroll
        for (int e = 0; e < 4; e++) aoRow[lane + 32*e] = 0.f;
        return;
    }
    const float* qr = g_q + ((long)b*LL + l)*DM + h*128;
    float sc = -1e30f;
    if (lane < tb) {
        const float* kr = g_k + (b*NCH + lane)*DM + h*128;
        float s = 0.f;
        #pragma unroll 4
        for (int kk = 0; kk < 128; kk++) s += qr[kk]*kr[kk];
        sc = s * 0.08838834764831845f;
    }
    float mx = sc;
    #pragma unroll
    for (int o = 16; o > 0; o >>= 1) mx = fmaxf(mx, __shfl_xor_sync(0xffffffffu, mx, o));
    float p = (lane < tb) ? __expf(sc - mx) : 0.f;
    float sum = p;
    #pragma unroll
    for (int o = 16; o > 0; o >>= 1) sum += __shfl_xor_sync(0xffffffffu, sum, o);
    float a = p / sum;
    float accv[4] = {0.f,0.f,0.f,0.f};
    for (int mm = 0; mm < tb; mm++) {
        float am = __shfl_sync(0xffffffffu, a, mm);
        const float* vr = g_v + (b*NCH + mm)*DM + h*128;
        #pragma unroll
        for (int e = 0; e < 4; e++) accv[e] += am * vr[lane + 32*e];
    }
    #pragma unroll
    for (int e = 0; e < 4; e++) aoRow[lane + 32*e] = accv[e];
}

__global__ void ln_k(const float* __restrict__ lw, const float* __restrict__ lb) {
    int r = blockIdx.x*4 + (threadIdx.x >> 5);
    int lane = threadIdx.x & 31;
    const float* src = g_hres + (long)r*DM;
    float vals[16]; float s1 = 0.f, s2 = 0.f;
    #pragma unroll
    for (int k2 = 0; k2 < 16; k2++) { float v = src[lane + 32*k2]; vals[k2] = v; s1 += v; s2 += v*v; }
    #pragma unroll
    for (int o = 16; o > 0; o >>= 1) {
        s1 += __shfl_xor_sync(0xffffffffu, s1, o);
        s2 += __shfl_xor_sync(0xffffffffu, s2, o);
    }
    float mu = s1 * (1.0f/DM);
    float var = s2 * (1.0f/DM) - mu*mu;
    float is = rsqrtf(var + 1e-5f);
    #pragma unroll
    for (int k2 = 0; k2 < 16; k2++) {
        int c = lane + 32*k2;
        g_hf[(long)r*DM + c] = (vals[k2] - mu)*is*lw[c] + lb[c];
    }
}

// ---------------- launcher ----------------
extern "C" void kernel_launch(void* const* d_in, const int* in_sizes, int n_in,
                              void* d_out, int out_size) {
    const int*   tokens = (const int*)  d_in[0];
    const float* embed  = (const float*)d_in[1];
    const float* rms_w  = (const float*)d_in[2];
    const float* W_in   = (const float*)d_in[3];
    const float* conv_w = (const float*)d_in[4];
    const float* conv_b = (const float*)d_in[5];
    const float* x_proj = (const float*)d_in[6];
    const float* dt_w   = (const float*)d_in[7];
    const float* dt_b   = (const float*)d_in[8];
    const float* A_log  = (const float*)d_in[9];
    const float* D_skip = (const float*)d_in[10];
    const float* W_out  = (const float*)d_in[11];
    const float* init_state = (const float*)d_in[12];
    const float* Wq = (const float*)d_in[13];
    const float* Wk = (const float*)d_in[14];
    const float* Wv = (const float*)d_in[15];
    const float* bq = (const float*)d_in[16];
    const float* bk = (const float*)d_in[17];
    const float* bv = (const float*)d_in[18];
    const float* Wo = (const float*)d_in[19];
    const float* bo = (const float*)d_in[20];
    const float* ln_w = (const float*)d_in[21];
    const float* ln_b = (const float*)d_in[22];
    const float* head_w = (const float*)d_in[23];
    float* out = (float*)d_out;

    embed_k<<<8192, 256>>>(tokens, embed);
    a2_k  <<<960,  256>>>(A_log);
    trans_k<<<4096, 256>>>(Wq, Wk, Wv, Wo);
    sinit_k<<<60,   256>>>(init_state);

    for (int d = 0; d < NCH + NLAY - 1; d++) {
        int i_min = d - (NLAY - 1); if (i_min < 0) i_min = 0;
        int i_max = (d < NCH - 1) ? d : NCH - 1;
        int nc = i_max - i_min + 1;
        prep_k<<<(nc*RWS + 3)/4, 128>>>(d, i_min, nc*RWS, rms_w);
        fgemm_k<10><<<dim3(32, nc), 256>>>(W_in, nullptr, nullptr, d, i_min, 2*DI, DM);
        tail_k<10><<<dim3(16, nc), 128>>>(W_in, d, i_min, 2*DI, DM);
        conv_k<<<dim3(520, nc), 256>>>(d, i_min, conv_w, conv_b);
        fgemm_k<11><<<dim3(1, nc), 256>>>(x_proj, nullptr, nullptr, d, i_min, 64, DI);
        tail_k<11><<<dim3(1, nc), 128>>>(x_proj, d, i_min, 64, DI);
        scan_k<<<nc*16, 128>>>(d, i_min, dt_w, dt_b, D_skip);
        fgemm_k<12><<<dim3(8, nc), 256>>>(W_out, nullptr, nullptr, d, i_min, DM, DI);
        tail_k<12><<<dim3(4, nc), 128>>>(W_out, d, i_min, DM, DI);
    }

    reorder_k<<<8192, 256>>>();
    fgemm_k<20><<<256, 256>>>(nullptr, nullptr, bq, 0, 0, DM, DM);
    gemm_k<21><<<8,   256>>>(nullptr, nullptr, nullptr, BB*NCH, DM, DM, bk, 0, 0);
    gemm_k<22><<<8,   256>>>(nullptr, nullptr, nullptr, BB*NCH, DM, DM, bv, 0, 0);
    attn_k<<<2048, 256>>>();
    fgemm_k<23><<<256, 256>>>(nullptr, nullptr, bo, 0, 0, DM, DM);
    ln_k<<<1024, 128>>>(ln_w, ln_b);
    fgemm_k<24><<<256, 256>>>(head_w, out, nullptr, 0, 0, DM, DM);
}